// round 16
// baseline (speedup 1.0000x reference)
#include <cuda_runtime.h>
#include <cuda_fp16.h>
#include <cstdint>

#define EPSC 1e-6f
#define PEPS 1e-5f
#define NMAX 100352
#define DDIM 64
#define CAP  128            // padded CSR row capacity (Poisson(32) rows; P(deg>=128) ~ 0)
#define SPAD 72             // padded smem row (halves): 144B stride, conflict-free ldmatrix

// Scratch (device globals; zero-initialized at load).
// g_cnt invariant: zero at entry to every kernel_launch (agg_final restores it).
__device__ float  g_e0 [(size_t)NMAX * DDIM];
__device__ __half g_h  [(size_t)NMAX * DDIM];  // layer-1 transformed features (fp16)
__device__ __half g_h2 [(size_t)NMAX * DDIM];  // layer-2 transformed features (fp16)
__device__ float  g_h1 [(size_t)NMAX * DDIM];  // layer-1 output (residual, fp32)
__device__ float  g_e0n2[NMAX];                // ||e0||^2 per row
__device__ float  g_h1n2[NMAX];                // ||h1||^2 per row
__device__ uint2  g_ecv[(size_t)NMAX * CAP];   // padded-CSR (col*64, dup-fp16 val); slots >= cnt stay 0
__device__ int    g_cnt[NMAX];                 // per-row cursor -> degree
__device__ float  g_bh1[DDIM];                 // proj(exp0(b1)) precomputed
__device__ float  g_bh2[DDIM];                 // proj(exp0(b2)) precomputed
__device__ float  g_bhn2[2];                   // ||bh1||^2, ||bh2||^2

// ---------- fast transcendentals ----------
__device__ __forceinline__ float fast_tanh(float x) {
    float e = __expf(x);
    return 1.f - __fdividef(2.f, e * e + 1.f);
}
__device__ __forceinline__ float fast_atanh(float n) {
    return 0.5f * __logf(__fdividef(1.f + n, 1.f - n));
}

// ---------- 16-lane row-group helpers ----------
__device__ __forceinline__ float grp_sum(float v) {
    v += __shfl_xor_sync(0xffffffffu, v, 1);
    v += __shfl_xor_sync(0xffffffffu, v, 2);
    v += __shfl_xor_sync(0xffffffffu, v, 4);
    v += __shfl_xor_sync(0xffffffffu, v, 8);
    return v;
}
__device__ __forceinline__ float d4(float4 a, float4 b) {
    return a.x*b.x + a.y*b.y + a.z*b.z + a.w*b.w;
}
__device__ __forceinline__ float4 s4(float4 a, float s) {
    return make_float4(a.x*s, a.y*s, a.z*s, a.w*s);
}
__device__ __forceinline__ float4 ld4(const float* p) { return *reinterpret_cast<const float4*>(p); }
__device__ __forceinline__ void   st4(float* p, float4 v) { *reinterpret_cast<float4*>(p) = v; }

// ---------- norm-tracking hyperbolic ops ----------
__device__ __forceinline__ float4 exp0proj(float4 a, float& no) {  // proj(exp0(a))
    float n2 = fmaxf(grp_sum(d4(a, a)), EPSC * EPSC);
    float rn = rsqrtf(n2);
    float n  = n2 * rn;
    float t  = fast_tanh(n);
    float p  = fminf(__fdividef(1.f - PEPS, t), 1.f);
    no = t * p;
    return s4(a, t * rn * p);
}
__device__ __forceinline__ float4 mob_k(float4 x, float4 y, float x2, float y2) {
    float xy = grp_sum(d4(x, y));
    float ca = 1.f + 2.f * xy + y2;
    float cb = 1.f - x2;
    float id = __fdividef(1.f, fmaxf(1.f + 2.f * xy + x2 * y2, EPSC));
    return make_float4((ca*x.x + cb*y.x) * id, (ca*x.y + cb*y.y) * id,
                       (ca*x.z + cb*y.z) * id, (ca*x.w + cb*y.w) * id);
}
__device__ __forceinline__ float4 projn(float4 m, float& no) {
    float n2 = fmaxf(grp_sum(d4(m, m)), EPSC * EPSC);
    float rn = rsqrtf(n2);
    float p  = fminf((1.f - PEPS) * rn, 1.f);
    no = n2 * rn * p;
    return s4(m, p);
}
__device__ __forceinline__ float4 projlog(float4 m) {
    float n2 = fmaxf(grp_sum(d4(m, m)), EPSC * EPSC);
    float rn = rsqrtf(n2);
    float nm = n2 * rn;
    float p  = fminf((1.f - PEPS) * rn, 1.f);
    float no = fminf(nm * p, 1.f - PEPS);
    float sc = p * __fdividef(fast_atanh(no), no);
    return s4(m, sc);
}
__device__ __forceinline__ float4 log0n(float4 o, float n) {
    float nc = fminf(n, 1.f - PEPS);
    return s4(o, __fdividef(fast_atanh(nc), fmaxf(n, EPSC)));
}

__device__ __forceinline__ __half2 u2h2(unsigned u) {
    __half2 h; *reinterpret_cast<unsigned*>(&h) = u; return h;
}
// float4 -> 4 halves (8B) store
__device__ __forceinline__ void sth4(__half* p, float4 v) {
    __half2 h01 = __floats2half2_rn(v.x, v.y);
    __half2 h23 = __floats2half2_rn(v.z, v.w);
    uint2 q = make_uint2(*reinterpret_cast<uint32_t*>(&h01),
                         *reinterpret_cast<uint32_t*>(&h23));
    *reinterpret_cast<uint2*>(p) = q;
}

// ---------- tensor-core primitives ----------
__device__ __forceinline__ uint32_t s2u(const void* p) {
    return (uint32_t)__cvta_generic_to_shared(p);
}
__device__ __forceinline__ void ldsm_x4(uint32_t& r0, uint32_t& r1, uint32_t& r2, uint32_t& r3,
                                        uint32_t addr) {
    asm volatile("ldmatrix.sync.aligned.m8n8.x4.shared.b16 {%0,%1,%2,%3}, [%4];"
                 : "=r"(r0), "=r"(r1), "=r"(r2), "=r"(r3) : "r"(addr));
}
__device__ __forceinline__ void ldsm_x4_t(uint32_t& r0, uint32_t& r1, uint32_t& r2, uint32_t& r3,
                                          uint32_t addr) {
    asm volatile("ldmatrix.sync.aligned.m8n8.x4.trans.shared.b16 {%0,%1,%2,%3}, [%4];"
                 : "=r"(r0), "=r"(r1), "=r"(r2), "=r"(r3) : "r"(addr));
}
__device__ __forceinline__ void mma_16816(float* c,
                                          uint32_t a0, uint32_t a1, uint32_t a2, uint32_t a3,
                                          uint32_t b0, uint32_t b1) {
    asm volatile("mma.sync.aligned.m16n8k16.row.col.f32.f16.f16.f32 "
                 "{%0,%1,%2,%3}, {%4,%5,%6,%7}, {%8,%9}, {%0,%1,%2,%3};"
                 : "+f"(c[0]), "+f"(c[1]), "+f"(c[2]), "+f"(c[3])
                 : "r"(a0), "r"(a1), "r"(a2), "r"(a3), "r"(b0), "r"(b1));
}

// ---------- tensor-core 64x64x64 GEMM: C(64,64) = A(64,64) @ W(64,64), fp16 in, fp16 out ----------
__device__ __forceinline__ void rowgemm_tc(const __half* Wsh, const __half* preh,
                                           int tid, int rowbase, int N,
                                           __half* __restrict__ hout) {
    int wid  = tid >> 5, lane = tid & 31;
    int wm   = wid & 3;
    int wn   = wid >> 2;
    int lr   = lane & 15;
    int lc   = (lane & 16) ? 8 : 0;
    float c[4][4];
#pragma unroll
    for (int t = 0; t < 4; t++) { c[t][0] = c[t][1] = c[t][2] = c[t][3] = 0.f; }

    uint32_t aBase = s2u(preh) + (uint32_t)(((wm * 16 + lr) * SPAD + lc) * 2);
    uint32_t bBase = s2u(Wsh)  + (uint32_t)((lr * SPAD + wn * 32 + lc) * 2);
#pragma unroll
    for (int kk = 0; kk < 4; kk++) {
        uint32_t a0, a1, a2, a3;
        ldsm_x4(a0, a1, a2, a3, aBase + kk * 32);
        uint32_t p0, p1, p2, p3, q0, q1, q2, q3;
        ldsm_x4_t(p0, p1, p2, p3, bBase + kk * 16 * SPAD * 2);
        ldsm_x4_t(q0, q1, q2, q3, bBase + kk * 16 * SPAD * 2 + 32);
        mma_16816(c[0], a0, a1, a2, a3, p0, p1);
        mma_16816(c[1], a0, a1, a2, a3, p2, p3);
        mma_16816(c[2], a0, a1, a2, a3, q0, q1);
        mma_16816(c[3], a0, a1, a2, a3, q2, q3);
    }
    int r0  = rowbase + wm * 16 + (lane >> 2);
    int col = wn * 32 + (lane & 3) * 2;
#pragma unroll
    for (int t = 0; t < 4; t++) {
        __half2 lo = __floats2half2_rn(c[t][0], c[t][1]);
        __half2 hi = __floats2half2_rn(c[t][2], c[t][3]);
        if (r0 < N)
            *reinterpret_cast<__half2*>(hout + (size_t)r0 * 64 + col + t * 8) = lo;
        if (r0 + 8 < N)
            *reinterpret_cast<__half2*>(hout + (size_t)(r0 + 8) * 64 + col + t * 8) = hi;
    }
}

// load fp32 W (64x64) into padded fp16 smem
__device__ __forceinline__ void loadW_h(__half* Wsh, const float* __restrict__ W, int tid) {
#pragma unroll
    for (int i = tid; i < 1024; i += 256) {
        int k = i >> 4, grp = i & 15;
        float4 w = ld4(W + k * 64 + grp * 4);
        sth4(Wsh + k * SPAD + grp * 4, w);
    }
}

// ---------- converged-warp aggregation: HFMA2 chunks, deep unroll, streaming records ----------
__device__ __forceinline__ float4 aggregate_row_cw(const __half* __restrict__ h,
                                                   int myrow, int sub) {
    const uint4* ep = reinterpret_cast<const uint4*>(g_ecv + (size_t)myrow * CAP);
    int cnt = min(g_cnt[myrow], CAP);
    int m   = max(cnt, __shfl_xor_sync(0xffffffffu, cnt, 16));
    int mc  = (m + 3) >> 2;
    int j   = sub * 4;
    float2 f0 = make_float2(0.f, 0.f), f1 = f0;
    #pragma unroll 4
    for (int c = 0; c < mc; c++) {
        uint4 p0 = __ldcs(&ep[2 * c]);         // evict-first: don't pollute L2
        uint4 p1 = __ldcs(&ep[2 * c + 1]);
        uint2 q0 = __ldg(reinterpret_cast<const uint2*>(h + (p0.x + j)));
        uint2 q1 = __ldg(reinterpret_cast<const uint2*>(h + (p0.z + j)));
        uint2 q2 = __ldg(reinterpret_cast<const uint2*>(h + (p1.x + j)));
        uint2 q3 = __ldg(reinterpret_cast<const uint2*>(h + (p1.z + j)));
        __half2 v0 = u2h2(p0.y), v1 = u2h2(p0.w);
        __half2 v2 = u2h2(p1.y), v3 = u2h2(p1.w);
        __half2 a0 = __hmul2(v0, u2h2(q0.x));
        __half2 a1 = __hmul2(v0, u2h2(q0.y));
        a0 = __hfma2(v1, u2h2(q1.x), a0);  a1 = __hfma2(v1, u2h2(q1.y), a1);
        a0 = __hfma2(v2, u2h2(q2.x), a0);  a1 = __hfma2(v2, u2h2(q2.y), a1);
        a0 = __hfma2(v3, u2h2(q3.x), a0);  a1 = __hfma2(v3, u2h2(q3.y), a1);
        float2 t0 = __half22float2(a0);
        float2 t1 = __half22float2(a1);
        f0.x += t0.x; f0.y += t0.y; f1.x += t1.x; f1.y += t1.y;
    }
    return make_float4(f0.x, f0.y, f1.x, f1.y);
}

// ---------- edge record helper: pack + streaming store ----------
__device__ __forceinline__ void store_edge(int r, int c, float v) {
    int pos = atomicAdd(&g_cnt[r], 1);
    if (pos < CAP) {
        unsigned hv = (unsigned)__half_as_ushort(__float2half_rn(v));
        unsigned long long rec = (unsigned long long)((unsigned)c << 6)
                               | ((unsigned long long)(hv * 0x10001u) << 32);
        __stcs(reinterpret_cast<unsigned long long*>(&g_ecv[(size_t)r * CAP + pos]), rec);
    }
}

// ---------- merged kernel: interleaved pre blocks (1 : s-1 with edge blocks) ----------
__global__ __launch_bounds__(256, 5) void pre_reorder_kernel(
        const float* __restrict__ x, const float* __restrict__ W,
        const int* __restrict__ rows, const int* __restrict__ cols,
        const float* __restrict__ vals,
        const float* __restrict__ b1, const float* __restrict__ b2,
        int N, int E, int rowBlocks, int s) {
    __shared__ __half Wsh [64 * SPAD];
    __shared__ __half preh[64 * SPAD];
    int tid = threadIdx.x;
    int bx  = blockIdx.x;
    int preId = bx / s;
    bool isPre = ((bx % s) == 0) && (preId < rowBlocks);

    if (!isPre) {
        // ---- edge reorder part: 4 edges/thread, 4 independent atomic->store chains ----
        int bid = bx - min((bx + s - 1) / s, rowBlocks);
        if (bid == 0 && tid < 64) {              // bh = proj(exp0(b)) + ||bh||^2
            int w   = tid >> 5;
            int sub = tid & 15;
            const float* b = w ? b2 : b1;
            float4 bv = ld4(b + sub * 4);
            float nb;
            float4 bh = exp0proj(bv, nb);
            if ((tid & 31) < 16) {
                st4((w ? g_bh2 : g_bh1) + sub * 4, bh);
                if (sub == 0) g_bhn2[w] = nb * nb;
            }
        }
        int e = (bid * 256 + tid) * 4;
        if (e + 3 < E) {
            int4   r4 = __ldg(reinterpret_cast<const int4*>(rows + e));
            int4   c4 = __ldg(reinterpret_cast<const int4*>(cols + e));
            float4 v4 = __ldg(reinterpret_cast<const float4*>(vals + e));
            store_edge(r4.x, c4.x, v4.x);
            store_edge(r4.y, c4.y, v4.y);
            store_edge(r4.z, c4.z, v4.z);
            store_edge(r4.w, c4.w, v4.w);
        } else {
            for (int k = e; k < E; k++)
                store_edge(rows[k], cols[k], vals[k]);
        }
        return;
    }

    // ---- pre part: 64 rows; e0 = proj(x); pre = log0(e0); g_h = half(pre @ W1) via HMMA ----
    loadW_h(Wsh, W, tid);

    int g    = tid >> 4;
    int sub  = tid & 15;
    int base = preId * 64;
#pragma unroll
    for (int rr = 0; rr < 4; rr++) {
        int row  = base + rr * 16 + g;
        int rowc = min(row, N - 1);
        size_t off = (size_t)rowc * 64 + sub * 4;
        float4 xv = __ldcs(reinterpret_cast<const float4*>(x + off));  // single-touch stream
        float ne0;
        float4 e0 = projn(xv, ne0);
        float4 pr = log0n(e0, ne0);
        if (row < N) {
            st4(g_e0 + off, e0);
            if (sub == 0) g_e0n2[row] = ne0 * ne0;
        }
        sth4(preh + (rr * 16 + g) * SPAD + sub * 4, pr);
    }
    __syncthreads();
    rowgemm_tc(Wsh, preh, tid, base, N, g_h);
}

// ---------- fused: aggregate layer-1 + epilogue + HMMA GEMM W2 -> g_h2 (64 rows/block) ----------
__global__ __launch_bounds__(256, 5) void agg_mid_kernel(const float* __restrict__ W2, int N) {
    __shared__ __half Wsh [64 * SPAD];
    __shared__ __half preh[64 * SPAD];
    int tid = threadIdx.x;
    loadW_h(Wsh, W2, tid);

    int g    = tid >> 4;
    int sub  = tid & 15;
    int base = blockIdx.x * 64;
    for (int rr = 0; rr < 4; rr++) {
        int row  = base + rr * 16 + g;
        int rowc = min(row, N - 1);
        size_t off = (size_t)rowc * 64 + sub * 4;

        float4 a = aggregate_row_cw(g_h, rowc, sub);

        float no;
        float4 o  = exp0proj(a, no);
        float4 bh = ld4(g_bh1 + sub * 4);
        float4 m1 = mob_k(o, bh, no * no, g_bhn2[0]);
        float4 l  = projlog(m1);
        float4 tv = make_float4(fast_tanh(l.x), fast_tanh(l.y),
                                fast_tanh(l.z), fast_tanh(l.w));
        float no3;
        float4 o3 = exp0proj(tv, no3);
        float4 e0 = ld4(g_e0 + off);
        float4 m2 = mob_k(o3, e0, no3 * no3, g_e0n2[rowc]);
        float nh1;
        float4 h1 = projn(m2, nh1);
        float4 pr = log0n(h1, nh1);
        if (row < N) {
            st4(g_h1 + off, h1);
            if (sub == 0) g_h1n2[row] = nh1 * nh1;
        }
        sth4(preh + (rr * 16 + g) * SPAD + sub * 4, pr);
    }
    __syncthreads();
    rowgemm_tc(Wsh, preh, tid, base, N, g_h2);
}

// ---------- fused: aggregate layer-2 + epilogue -> out; restores g_cnt = 0 ----------
__global__ __launch_bounds__(256, 6) void agg_final_kernel(float* __restrict__ out, int N) {
    int tid  = threadIdx.x;
    int rl   = tid >> 4;
    int sub  = tid & 15;
    int row  = blockIdx.x * 16 + rl;
    int rowc = min(row, N - 1);
    size_t off = (size_t)rowc * 64 + sub * 4;

    float4 a = aggregate_row_cw(g_h2, rowc, sub);

    float no;
    float4 o  = exp0proj(a, no);
    float4 bh = ld4(g_bh2 + sub * 4);
    float4 m1 = mob_k(o, bh, no * no, g_bhn2[1]);
    float nob;
    float4 ob = projn(m1, nob);
    float4 h1 = ld4(g_h1 + off);
    float4 m2 = mob_k(ob, h1, nob * nob, g_h1n2[rowc]);
    float nf;
    float4 h2 = projn(m2, nf);
    if (row < N) {
        st4(out + off, h2);
        if (sub == 0) g_cnt[row] = 0;          // restore invariant for next call
    }
}

extern "C" void kernel_launch(void* const* d_in, const int* in_sizes, int n_in,
                              void* d_out, int out_size) {
    const float* x    = (const float*)d_in[0];
    const float* vals = (const float*)d_in[1];
    const float* W1   = (const float*)d_in[2];
    const float* b1   = (const float*)d_in[3];
    const float* W2   = (const float*)d_in[4];
    const float* b2   = (const float*)d_in[5];
    const int*   rows = (const int*)d_in[6];
    const int*   cols = (const int*)d_in[7];
    int N = in_sizes[0] / 64;
    int E = in_sizes[1];
    float* out = (float*)d_out;

    int rowBlocks64 = (N + 63) / 64;
    int rowBlocks16 = (N + 15) / 16;
    int edgeBlocks  = (E / 4 + 255) / 256;     // 4 edges per thread
    int total       = rowBlocks64 + edgeBlocks;
    int s           = total / rowBlocks64; if (s < 1) s = 1;

    // 3-launch pipeline: (pre ⊗ reorder interleaved) -> agg1 -> agg2(+counter reset)
    pre_reorder_kernel<<<total, 256>>>(x, W1, rows, cols, vals, b1, b2,
                                       N, E, rowBlocks64, s);
    agg_mid_kernel<<<rowBlocks64, 256>>>(W2, N);
    agg_final_kernel<<<rowBlocks16, 256>>>(out, N);
}

// round 17
// speedup vs baseline: 1.0609x; 1.0609x over previous
#include <cuda_runtime.h>
#include <cuda_fp16.h>
#include <cstdint>

#define EPSC 1e-6f
#define PEPS 1e-5f
#define NMAX 100352
#define DDIM 64
#define CAP  128            // padded CSR row capacity (Poisson(32) rows; P(deg>=128) ~ 0)
#define SPAD 72             // padded smem row (halves): 144B stride, conflict-free ldmatrix

// Scratch (device globals; zero-initialized at load).
// g_cnt invariant: zero at entry to every kernel_launch (agg_final restores it).
__device__ float  g_e0 [(size_t)NMAX * DDIM];
__device__ __half g_h  [(size_t)NMAX * DDIM];  // layer-1 transformed features (fp16)
__device__ __half g_h2 [(size_t)NMAX * DDIM];  // layer-2 transformed features (fp16)
__device__ float  g_h1 [(size_t)NMAX * DDIM];  // layer-1 output (residual, fp32)
__device__ float  g_e0n2[NMAX];                // ||e0||^2 per row
__device__ float  g_h1n2[NMAX];                // ||h1||^2 per row
__device__ uint2  g_ecv[(size_t)NMAX * CAP];   // padded-CSR (col*64, dup-fp16 val); slots >= cnt stay 0
__device__ int    g_cnt[NMAX];                 // per-row cursor -> degree
__device__ float  g_bh1[DDIM];                 // proj(exp0(b1)) precomputed
__device__ float  g_bh2[DDIM];                 // proj(exp0(b2)) precomputed
__device__ float  g_bhn2[2];                   // ||bh1||^2, ||bh2||^2

// ---------- fast transcendentals ----------
__device__ __forceinline__ float fast_tanh(float x) {
    float e = __expf(x);
    return 1.f - __fdividef(2.f, e * e + 1.f);
}
__device__ __forceinline__ float fast_atanh(float n) {
    return 0.5f * __logf(__fdividef(1.f + n, 1.f - n));
}

// ---------- 16-lane row-group helpers ----------
__device__ __forceinline__ float grp_sum(float v) {
    v += __shfl_xor_sync(0xffffffffu, v, 1);
    v += __shfl_xor_sync(0xffffffffu, v, 2);
    v += __shfl_xor_sync(0xffffffffu, v, 4);
    v += __shfl_xor_sync(0xffffffffu, v, 8);
    return v;
}
__device__ __forceinline__ float d4(float4 a, float4 b) {
    return a.x*b.x + a.y*b.y + a.z*b.z + a.w*b.w;
}
__device__ __forceinline__ float4 s4(float4 a, float s) {
    return make_float4(a.x*s, a.y*s, a.z*s, a.w*s);
}
__device__ __forceinline__ float4 ld4(const float* p) { return *reinterpret_cast<const float4*>(p); }
__device__ __forceinline__ void   st4(float* p, float4 v) { *reinterpret_cast<float4*>(p) = v; }

// ---------- norm-tracking hyperbolic ops ----------
__device__ __forceinline__ float4 exp0proj(float4 a, float& no) {  // proj(exp0(a))
    float n2 = fmaxf(grp_sum(d4(a, a)), EPSC * EPSC);
    float rn = rsqrtf(n2);
    float n  = n2 * rn;
    float t  = fast_tanh(n);
    float p  = fminf(__fdividef(1.f - PEPS, t), 1.f);
    no = t * p;
    return s4(a, t * rn * p);
}
__device__ __forceinline__ float4 mob_k(float4 x, float4 y, float x2, float y2) {
    float xy = grp_sum(d4(x, y));
    float ca = 1.f + 2.f * xy + y2;
    float cb = 1.f - x2;
    float id = __fdividef(1.f, fmaxf(1.f + 2.f * xy + x2 * y2, EPSC));
    return make_float4((ca*x.x + cb*y.x) * id, (ca*x.y + cb*y.y) * id,
                       (ca*x.z + cb*y.z) * id, (ca*x.w + cb*y.w) * id);
}
__device__ __forceinline__ float4 projn(float4 m, float& no) {
    float n2 = fmaxf(grp_sum(d4(m, m)), EPSC * EPSC);
    float rn = rsqrtf(n2);
    float p  = fminf((1.f - PEPS) * rn, 1.f);
    no = n2 * rn * p;
    return s4(m, p);
}
__device__ __forceinline__ float4 projlog(float4 m) {
    float n2 = fmaxf(grp_sum(d4(m, m)), EPSC * EPSC);
    float rn = rsqrtf(n2);
    float nm = n2 * rn;
    float p  = fminf((1.f - PEPS) * rn, 1.f);
    float no = fminf(nm * p, 1.f - PEPS);
    float sc = p * __fdividef(fast_atanh(no), no);
    return s4(m, sc);
}
__device__ __forceinline__ float4 log0n(float4 o, float n) {
    float nc = fminf(n, 1.f - PEPS);
    return s4(o, __fdividef(fast_atanh(nc), fmaxf(n, EPSC)));
}

__device__ __forceinline__ __half2 u2h2(unsigned u) {
    __half2 h; *reinterpret_cast<unsigned*>(&h) = u; return h;
}
// float4 -> 4 halves (8B) store
__device__ __forceinline__ void sth4(__half* p, float4 v) {
    __half2 h01 = __floats2half2_rn(v.x, v.y);
    __half2 h23 = __floats2half2_rn(v.z, v.w);
    uint2 q = make_uint2(*reinterpret_cast<uint32_t*>(&h01),
                         *reinterpret_cast<uint32_t*>(&h23));
    *reinterpret_cast<uint2*>(p) = q;
}

// ---------- tensor-core primitives ----------
__device__ __forceinline__ uint32_t s2u(const void* p) {
    return (uint32_t)__cvta_generic_to_shared(p);
}
__device__ __forceinline__ void ldsm_x4(uint32_t& r0, uint32_t& r1, uint32_t& r2, uint32_t& r3,
                                        uint32_t addr) {
    asm volatile("ldmatrix.sync.aligned.m8n8.x4.shared.b16 {%0,%1,%2,%3}, [%4];"
                 : "=r"(r0), "=r"(r1), "=r"(r2), "=r"(r3) : "r"(addr));
}
__device__ __forceinline__ void ldsm_x4_t(uint32_t& r0, uint32_t& r1, uint32_t& r2, uint32_t& r3,
                                          uint32_t addr) {
    asm volatile("ldmatrix.sync.aligned.m8n8.x4.trans.shared.b16 {%0,%1,%2,%3}, [%4];"
                 : "=r"(r0), "=r"(r1), "=r"(r2), "=r"(r3) : "r"(addr));
}
__device__ __forceinline__ void mma_16816(float* c,
                                          uint32_t a0, uint32_t a1, uint32_t a2, uint32_t a3,
                                          uint32_t b0, uint32_t b1) {
    asm volatile("mma.sync.aligned.m16n8k16.row.col.f32.f16.f16.f32 "
                 "{%0,%1,%2,%3}, {%4,%5,%6,%7}, {%8,%9}, {%0,%1,%2,%3};"
                 : "+f"(c[0]), "+f"(c[1]), "+f"(c[2]), "+f"(c[3])
                 : "r"(a0), "r"(a1), "r"(a2), "r"(a3), "r"(b0), "r"(b1));
}

// ---------- tensor-core 64x64x64 GEMM: C(64,64) = A(64,64) @ W(64,64), fp16 in, fp16 out ----------
__device__ __forceinline__ void rowgemm_tc(const __half* Wsh, const __half* preh,
                                           int tid, int rowbase, int N,
                                           __half* __restrict__ hout) {
    int wid  = tid >> 5, lane = tid & 31;
    int wm   = wid & 3;
    int wn   = wid >> 2;
    int lr   = lane & 15;
    int lc   = (lane & 16) ? 8 : 0;
    float c[4][4];
#pragma unroll
    for (int t = 0; t < 4; t++) { c[t][0] = c[t][1] = c[t][2] = c[t][3] = 0.f; }

    uint32_t aBase = s2u(preh) + (uint32_t)(((wm * 16 + lr) * SPAD + lc) * 2);
    uint32_t bBase = s2u(Wsh)  + (uint32_t)((lr * SPAD + wn * 32 + lc) * 2);
#pragma unroll
    for (int kk = 0; kk < 4; kk++) {
        uint32_t a0, a1, a2, a3;
        ldsm_x4(a0, a1, a2, a3, aBase + kk * 32);
        uint32_t p0, p1, p2, p3, q0, q1, q2, q3;
        ldsm_x4_t(p0, p1, p2, p3, bBase + kk * 16 * SPAD * 2);
        ldsm_x4_t(q0, q1, q2, q3, bBase + kk * 16 * SPAD * 2 + 32);
        mma_16816(c[0], a0, a1, a2, a3, p0, p1);
        mma_16816(c[1], a0, a1, a2, a3, p2, p3);
        mma_16816(c[2], a0, a1, a2, a3, q0, q1);
        mma_16816(c[3], a0, a1, a2, a3, q2, q3);
    }
    int r0  = rowbase + wm * 16 + (lane >> 2);
    int col = wn * 32 + (lane & 3) * 2;
#pragma unroll
    for (int t = 0; t < 4; t++) {
        __half2 lo = __floats2half2_rn(c[t][0], c[t][1]);
        __half2 hi = __floats2half2_rn(c[t][2], c[t][3]);
        if (r0 < N)
            *reinterpret_cast<__half2*>(hout + (size_t)r0 * 64 + col + t * 8) = lo;
        if (r0 + 8 < N)
            *reinterpret_cast<__half2*>(hout + (size_t)(r0 + 8) * 64 + col + t * 8) = hi;
    }
}

// load fp32 W (64x64) into padded fp16 smem
__device__ __forceinline__ void loadW_h(__half* Wsh, const float* __restrict__ W, int tid) {
#pragma unroll
    for (int i = tid; i < 1024; i += 256) {
        int k = i >> 4, grp = i & 15;
        float4 w = ld4(W + k * 64 + grp * 4);
        sth4(Wsh + k * SPAD + grp * 4, w);
    }
}

// ---------- converged-warp aggregation: HFMA2 chunks, deep unroll, streaming records ----------
__device__ __forceinline__ float4 aggregate_row_cw(const __half* __restrict__ h,
                                                   int myrow, int sub) {
    const uint4* ep = reinterpret_cast<const uint4*>(g_ecv + (size_t)myrow * CAP);
    int cnt = min(g_cnt[myrow], CAP);
    int m   = max(cnt, __shfl_xor_sync(0xffffffffu, cnt, 16));
    int mc  = (m + 3) >> 2;
    int j   = sub * 4;
    float2 f0 = make_float2(0.f, 0.f), f1 = f0;
    #pragma unroll 4
    for (int c = 0; c < mc; c++) {
        uint4 p0 = __ldcs(&ep[2 * c]);         // evict-first on READ side only
        uint4 p1 = __ldcs(&ep[2 * c + 1]);
        uint2 q0 = __ldg(reinterpret_cast<const uint2*>(h + (p0.x + j)));
        uint2 q1 = __ldg(reinterpret_cast<const uint2*>(h + (p0.z + j)));
        uint2 q2 = __ldg(reinterpret_cast<const uint2*>(h + (p1.x + j)));
        uint2 q3 = __ldg(reinterpret_cast<const uint2*>(h + (p1.z + j)));
        __half2 v0 = u2h2(p0.y), v1 = u2h2(p0.w);
        __half2 v2 = u2h2(p1.y), v3 = u2h2(p1.w);
        __half2 a0 = __hmul2(v0, u2h2(q0.x));
        __half2 a1 = __hmul2(v0, u2h2(q0.y));
        a0 = __hfma2(v1, u2h2(q1.x), a0);  a1 = __hfma2(v1, u2h2(q1.y), a1);
        a0 = __hfma2(v2, u2h2(q2.x), a0);  a1 = __hfma2(v2, u2h2(q2.y), a1);
        a0 = __hfma2(v3, u2h2(q3.x), a0);  a1 = __hfma2(v3, u2h2(q3.y), a1);
        float2 t0 = __half22float2(a0);
        float2 t1 = __half22float2(a1);
        f0.x += t0.x; f0.y += t0.y; f1.x += t1.x; f1.y += t1.y;
    }
    return make_float4(f0.x, f0.y, f1.x, f1.y);
}

// ---------- edge record helper: pack + PLAIN store (records must stay L2-resident) ----------
__device__ __forceinline__ void store_edge(int r, int c, float v) {
    int pos = atomicAdd(&g_cnt[r], 1);
    if (pos < CAP) {
        unsigned hv = (unsigned)__half_as_ushort(__float2half_rn(v));
        g_ecv[(size_t)r * CAP + pos] = make_uint2((unsigned)c << 6, hv * 0x10001u);
    }
}

// ---------- merged kernel: interleaved pre blocks (1 : s-1 with edge blocks) ----------
__global__ __launch_bounds__(256, 5) void pre_reorder_kernel(
        const float* __restrict__ x, const float* __restrict__ W,
        const int* __restrict__ rows, const int* __restrict__ cols,
        const float* __restrict__ vals,
        const float* __restrict__ b1, const float* __restrict__ b2,
        int N, int E, int rowBlocks, int s) {
    __shared__ __half Wsh [64 * SPAD];
    __shared__ __half preh[64 * SPAD];
    int tid = threadIdx.x;
    int bx  = blockIdx.x;
    int preId = bx / s;
    bool isPre = ((bx % s) == 0) && (preId < rowBlocks);

    if (!isPre) {
        // ---- edge reorder part: 4 edges/thread, 4 independent atomic->store chains ----
        int bid = bx - min((bx + s - 1) / s, rowBlocks);
        if (bid == 0 && tid < 64) {              // bh = proj(exp0(b)) + ||bh||^2
            int w   = tid >> 5;
            int sub = tid & 15;
            const float* b = w ? b2 : b1;
            float4 bv = ld4(b + sub * 4);
            float nb;
            float4 bh = exp0proj(bv, nb);
            if ((tid & 31) < 16) {
                st4((w ? g_bh2 : g_bh1) + sub * 4, bh);
                if (sub == 0) g_bhn2[w] = nb * nb;
            }
        }
        int e = (bid * 256 + tid) * 4;
        if (e + 3 < E) {
            int4   r4 = __ldg(reinterpret_cast<const int4*>(rows + e));
            int4   c4 = __ldg(reinterpret_cast<const int4*>(cols + e));
            float4 v4 = __ldg(reinterpret_cast<const float4*>(vals + e));
            store_edge(r4.x, c4.x, v4.x);
            store_edge(r4.y, c4.y, v4.y);
            store_edge(r4.z, c4.z, v4.z);
            store_edge(r4.w, c4.w, v4.w);
        } else {
            for (int k = e; k < E; k++)
                store_edge(rows[k], cols[k], vals[k]);
        }
        return;
    }

    // ---- pre part: 64 rows; e0 = proj(x); pre = log0(e0); g_h = half(pre @ W1) via HMMA ----
    loadW_h(Wsh, W, tid);

    int g    = tid >> 4;
    int sub  = tid & 15;
    int base = preId * 64;
#pragma unroll
    for (int rr = 0; rr < 4; rr++) {
        int row  = base + rr * 16 + g;
        int rowc = min(row, N - 1);
        size_t off = (size_t)rowc * 64 + sub * 4;
        float4 xv = ld4(x + off);
        float ne0;
        float4 e0 = projn(xv, ne0);
        float4 pr = log0n(e0, ne0);
        if (row < N) {
            st4(g_e0 + off, e0);
            if (sub == 0) g_e0n2[row] = ne0 * ne0;
        }
        sth4(preh + (rr * 16 + g) * SPAD + sub * 4, pr);
    }
    __syncthreads();
    rowgemm_tc(Wsh, preh, tid, base, N, g_h);
}

// ---------- fused: aggregate layer-1 + epilogue + HMMA GEMM W2 -> g_h2 (64 rows/block) ----------
__global__ __launch_bounds__(256, 4) void agg_mid_kernel(const float* __restrict__ W2, int N) {
    __shared__ __half Wsh [64 * SPAD];
    __shared__ __half preh[64 * SPAD];
    int tid = threadIdx.x;
    loadW_h(Wsh, W2, tid);

    int g    = tid >> 4;
    int sub  = tid & 15;
    int base = blockIdx.x * 64;
    for (int rr = 0; rr < 4; rr++) {
        int row  = base + rr * 16 + g;
        int rowc = min(row, N - 1);
        size_t off = (size_t)rowc * 64 + sub * 4;

        float4 a = aggregate_row_cw(g_h, rowc, sub);

        float no;
        float4 o  = exp0proj(a, no);
        float4 bh = ld4(g_bh1 + sub * 4);
        float4 m1 = mob_k(o, bh, no * no, g_bhn2[0]);
        float4 l  = projlog(m1);
        float4 tv = make_float4(fast_tanh(l.x), fast_tanh(l.y),
                                fast_tanh(l.z), fast_tanh(l.w));
        float no3;
        float4 o3 = exp0proj(tv, no3);
        float4 e0 = ld4(g_e0 + off);
        float4 m2 = mob_k(o3, e0, no3 * no3, g_e0n2[rowc]);
        float nh1;
        float4 h1 = projn(m2, nh1);
        float4 pr = log0n(h1, nh1);
        if (row < N) {
            st4(g_h1 + off, h1);
            if (sub == 0) g_h1n2[row] = nh1 * nh1;
        }
        sth4(preh + (rr * 16 + g) * SPAD + sub * 4, pr);
    }
    __syncthreads();
    rowgemm_tc(Wsh, preh, tid, base, N, g_h2);
}

// ---------- fused: aggregate layer-2 + epilogue -> out; restores g_cnt = 0 ----------
__global__ __launch_bounds__(256, 6) void agg_final_kernel(float* __restrict__ out, int N) {
    int tid  = threadIdx.x;
    int rl   = tid >> 4;
    int sub  = tid & 15;
    int row  = blockIdx.x * 16 + rl;
    int rowc = min(row, N - 1);
    size_t off = (size_t)rowc * 64 + sub * 4;

    float4 a = aggregate_row_cw(g_h2, rowc, sub);

    float no;
    float4 o  = exp0proj(a, no);
    float4 bh = ld4(g_bh2 + sub * 4);
    float4 m1 = mob_k(o, bh, no * no, g_bhn2[1]);
    float nob;
    float4 ob = projn(m1, nob);
    float4 h1 = ld4(g_h1 + off);
    float4 m2 = mob_k(ob, h1, nob * nob, g_h1n2[rowc]);
    float nf;
    float4 h2 = projn(m2, nf);
    if (row < N) {
        st4(out + off, h2);
        if (sub == 0) g_cnt[row] = 0;          // restore invariant for next call
    }
}

extern "C" void kernel_launch(void* const* d_in, const int* in_sizes, int n_in,
                              void* d_out, int out_size) {
    const float* x    = (const float*)d_in[0];
    const float* vals = (const float*)d_in[1];
    const float* W1   = (const float*)d_in[2];
    const float* b1   = (const float*)d_in[3];
    const float* W2   = (const float*)d_in[4];
    const float* b2   = (const float*)d_in[5];
    const int*   rows = (const int*)d_in[6];
    const int*   cols = (const int*)d_in[7];
    int N = in_sizes[0] / 64;
    int E = in_sizes[1];
    float* out = (float*)d_out;

    int rowBlocks64 = (N + 63) / 64;
    int rowBlocks16 = (N + 15) / 16;
    int edgeBlocks  = (E / 4 + 255) / 256;     // 4 edges per thread
    int total       = rowBlocks64 + edgeBlocks;
    int s           = total / rowBlocks64; if (s < 1) s = 1;

    // 3-launch pipeline: (pre ⊗ reorder interleaved) -> agg1 -> agg2(+counter reset)
    pre_reorder_kernel<<<total, 256>>>(x, W1, rows, cols, vals, b1, b2,
                                       N, E, rowBlocks64, s);
    agg_mid_kernel<<<rowBlocks64, 256>>>(W2, N);
    agg_final_kernel<<<rowBlocks16, 256>>>(out, N);
}